// round 7
// baseline (speedup 1.0000x reference)
#include <cuda_runtime.h>
#include <math.h>

#define N_SAMPLES   65536
#define N_FRAMES    128
#define NUM_COEFF   6
#define NUM_ACTIVE  7
#define NSER        7
#define NSTAGE      5        // staging slots (4 cp.async groups in flight)

// ---------------- device scratch (no allocation allowed) ----------------
__device__ float  g_y[NSER][N_FRAMES];
__device__ float  g_M[NSER][N_FRAMES];
__device__ float4 g_A[N_SAMPLES];        // taps v0..v3 (pre-negated)
__device__ float4 g_B[N_SAMPLES];        // taps v4,v5,v6, x
__device__ int    g_P[N_SAMPLES];        // ((t-1-z) & 1023) + 1024  (ring base, high copy)
__device__ int    g_minz;
__device__ int    g_maxz;
__device__ int    g_flag;

// ---------------- kernel A: coeff frames + spline tridiagonal solves ----------------
__global__ void prep_kernel(const float* __restrict__ delay,
                            const float* __restrict__ raw_gain,
                            const float* __restrict__ raw_coeff)
{
    __shared__ float s_y[NSER][N_FRAMES];
    __shared__ float s_cp[N_FRAMES];
    __shared__ float s_d[NSER][N_FRAMES];
    __shared__ float s_gain;

    const int tid = threadIdx.x;

    if (tid == 0) {
        s_gain = 1.0f / (1.0f + expf(-raw_gain[0]));
        g_minz = 0x7fffffff;
        g_maxz = 0;
        g_flag = 0;
        float c = 0.25f;
        s_cp[0] = c;
        for (int i = 1; i < N_FRAMES - 2; i++) {
            c = 1.0f / (4.0f - c);
            s_cp[i] = c;
        }
    }
    __syncthreads();

    for (int i = tid; i < N_FRAMES * NUM_COEFF; i += blockDim.x) {
        int r = i / NUM_COEFF, c = i % NUM_COEFF;
        s_y[1 + c][r] = 1.0f / (1.0f + expf(-raw_coeff[i]));
    }
    for (int r = tid; r < N_FRAMES; r += blockDim.x)
        s_y[0][r] = delay[r];
    __syncthreads();

    for (int r = tid; r < N_FRAMES; r += blockDim.x) {
        float sum = 0.0f;
        #pragma unroll
        for (int c = 0; c < NUM_COEFF; c++) sum += s_y[1 + c][r];
        float scale = s_gain / sum;
        #pragma unroll
        for (int c = 0; c < NUM_COEFF; c++) s_y[1 + c][r] *= scale;
    }
    __syncthreads();

    if (tid < NSER) {
        const int m = N_FRAMES - 2;
        const float K = 6.0f * 127.0f * 127.0f;
        float* y = s_y[tid];
        float* d = s_d[tid];

        float dp = K * (y[2] - 2.0f * y[1] + y[0]) * 0.25f;
        d[0] = dp;
        for (int i = 1; i < m; i++) {
            float rhs = K * (y[i + 2] - 2.0f * y[i + 1] + y[i]);
            dp = (rhs - dp) * s_cp[i];
            d[i] = dp;
        }
        g_M[tid][0] = 0.0f;
        g_M[tid][N_FRAMES - 1] = 0.0f;
        float Mn = 0.0f;
        for (int i = m - 1; i >= 0; i--) {
            Mn = d[i] - s_cp[i] * Mn;
            g_M[tid][i + 1] = Mn;
        }
    }
    __syncthreads();

    for (int i = tid; i < NSER * N_FRAMES; i += blockDim.x)
        (&g_y[0][0])[i] = (&s_y[0][0])[i];
}

// ---------------- kernel B: per-sample spline eval + tap weights ----------------
__global__ void sample_kernel(const float* __restrict__ exc,
                              const float* __restrict__ burst)
{
    const int t = blockIdx.x * blockDim.x + threadIdx.x;
    if (t >= N_SAMPLES) return;

    const float tt = (float)t * (1.0f / 65535.0f);
    int idx = (int)floorf(tt * 127.0f);
    idx = max(0, min(idx, 126));
    const float s  = tt - (float)idx * (1.0f / 127.0f);
    const float s2 = s * s;
    const float s3 = s2 * s;

    float vout[NSER];
    #pragma unroll
    for (int c = 0; c < NSER; c++) {
        float yi  = g_y[c][idx];
        float yi1 = g_y[c][idx + 1];
        float Mi  = g_M[c][idx];
        float Mi1 = g_M[c][idx + 1];
        float bsl = (yi1 - yi) * 127.0f - (2.0f * Mi + Mi1) * (1.0f / 762.0f);
        vout[c] = yi + bsl * s + 0.5f * Mi * s2 + (Mi1 - Mi) * s3 * (127.0f / 6.0f);
    }

    const float delay_i = vout[0];
    const int   z    = (int)floorf(delay_i);
    const float alfa = delay_i - (float)z;
    const float oma  = 1.0f - alfa;

    float v[7];
    v[0] = -oma * vout[1];
    #pragma unroll
    for (int k = 1; k < NUM_COEFF; k++)
        v[k] = -(alfa * vout[k] + oma * vout[k + 1]);
    v[6] = -alfa * vout[NUM_COEFF];

    g_A[t] = make_float4(v[0], v[1], v[2], v[3]);
    g_B[t] = make_float4(v[4], v[5], v[6], burst[t]);  // .w = x
    g_P[t] = ((t - 1 - z) & 1023) + 1024;              // ready-to-use LDS base

    if (exc[t] != 0.0f) atomicExch(&g_flag, 1);

    int wmin = __reduce_min_sync(0xffffffffu, z);
    int wmax = __reduce_max_sync(0xffffffffu, z);
    if ((threadIdx.x & 31) == 0) {
        atomicMin(&g_minz, wmin);
        atomicMax(&g_maxz, wmax);
    }
}

// ---------------- kernel B2: general exc IIR fallback ----------------
__global__ void exc_scan_kernel(const float* __restrict__ exc,
                                const float* __restrict__ burst)
{
    if (g_flag) {
        float ym1 = 0.0f;
        for (int t = 0; t < N_SAMPLES; t++) {
            ym1 = burst[t] - exc[t] * ym1;
            g_B[t].w = ym1;
        }
    }
}

// ---------------- cp.async helpers ----------------
__device__ __forceinline__ void cpa16(void* dst_smem, const void* src) {
    unsigned d = (unsigned)__cvta_generic_to_shared(dst_smem);
    asm volatile("cp.async.ca.shared.global [%0], [%1], 16;"
                 :: "r"(d), "l"(src) : "memory");
}
__device__ __forceinline__ void cpa4(void* dst_smem, const void* src) {
    unsigned d = (unsigned)__cvta_generic_to_shared(dst_smem);
    asm volatile("cp.async.ca.shared.global [%0], [%1], 4;"
                 :: "r"(d), "l"(src) : "memory");
}

// ---------------- kernel C: chunk-parallel Karplus-Strong scan -------------
// 4 warps, one sample per thread per chunk. Payload prefetched global->smem
// via cp.async (5 slots, 4 groups in flight), AND the current chunk's payload
// is held in REGISTERS: each iteration computes straight off registers after
// the barrier (ring LDS issues in cycle 1 — no dependent payload-LDS hop),
// then loads chunk c+1's payload from smem into registers, hiding that LDS
// latency under the next barrier. wait_group guards a group issued 4
// iterations earlier -> effectively free.
// Slot reuse safety: the cp.async at iteration c targets stX[slot][tid],
// which only thread tid ever reads, and tid's register-load of that slot
// happened at iteration c-2 (program order). Ring duplication / index-
// aliasing arguments unchanged from R5.
__global__ void __launch_bounds__(128, 1) ks_kernel(float* __restrict__ out)
{
    __shared__ float  ring[2048];
    __shared__ float4 stA[NSTAGE][128];
    __shared__ float4 stB[NSTAGE][128];
    __shared__ int    stP[NSTAGE][128];
    __shared__ int    sL;

    const int tid = threadIdx.x;
    #pragma unroll
    for (int i = tid; i < 2048; i += 128) ring[i] = 0.0f;

    if (tid == 0) {
        int L = g_minz + 1;
        if (L > 128) L = 128;
        int cap = 1024 - (g_maxz + NUM_ACTIVE) - 1;
        if (L > cap) L = cap;
        if (L < 1)  L = 1;
        sL = L;
    }
    __syncthreads();
    const int  L  = sL;
    const bool on = (tid < L);
    const int  nChunks = (N_SAMPLES + L - 1) / L;

    // prologue: issue groups for chunks 0..3 into slots 0..3
    #pragma unroll
    for (int s = 0; s < NSTAGE - 1; s++) {
        const int t = s * L + tid;
        if (on) {
            cpa16(&stA[s][tid], &g_A[t]);
            cpa16(&stB[s][tid], &g_B[t]);
            cpa4 (&stP[s][tid], &g_P[t]);
        }
        asm volatile("cp.async.commit_group;" ::: "memory");
    }

    // register payload for chunk 0
    float4 ca = make_float4(0, 0, 0, 0), cb = make_float4(0, 0, 0, 0);
    int    cp = 1024;
    asm volatile("cp.async.wait_group 3;" ::: "memory");
    if (on) { ca = stA[0][tid]; cb = stB[0][tid]; cp = stP[0][tid]; }
    __syncthreads();

    int    slot = tid & 1023;                  // ring write slot (low copy)
    float* outp = out + tid;

    for (int c0 = 0; c0 < nChunks; c0 += NSTAGE) {
        #pragma unroll
        for (int s = 0; s < NSTAGE; s++) {
            const int c = c0 + s;
            if (c < nChunks) {
                // ---- compute chunk c straight off registers ----
                const int t = c * L + tid;
                if (on && t < N_SAMPLES) {
                    float r0 = ring[cp    ];
                    float r1 = ring[cp - 1];
                    float r2 = ring[cp - 2];
                    float r3 = ring[cp - 3];
                    float r4 = ring[cp - 4];
                    float r5 = ring[cp - 5];
                    float r6 = ring[cp - 6];
                    float m0 = fmaf(ca.x, r0, ca.y * r1);
                    float m1 = fmaf(ca.z, r2, ca.w * r3);
                    float m2 = fmaf(cb.x, r4, cb.y * r5);
                    float m3 = cb.z * r6;
                    float y  = cb.w - ((m0 + m1) + (m2 + m3));
                    ring[slot]        = y;
                    ring[slot + 1024] = y;
                    *outp = y;
                }

                // ---- prefetch chunk c+4 into slot (s+4)%NSTAGE ----
                const int tp = (c + NSTAGE - 1) * L + tid;
                if (on && tp < N_SAMPLES) {
                    cpa16(&stA[(s + NSTAGE - 1) % NSTAGE][tid], &g_A[tp]);
                    cpa16(&stB[(s + NSTAGE - 1) % NSTAGE][tid], &g_B[tp]);
                    cpa4 (&stP[(s + NSTAGE - 1) % NSTAGE][tid], &g_P[tp]);
                }
                asm volatile("cp.async.commit_group;" ::: "memory");

                // ---- stage chunk c+1 payload into registers ----
                asm volatile("cp.async.wait_group 3;" ::: "memory");
                if (on && (c + 1) < nChunks) {
                    ca = stA[(s + 1) % NSTAGE][tid];
                    cb = stB[(s + 1) % NSTAGE][tid];
                    cp = stP[(s + 1) % NSTAGE][tid];
                }
                __syncthreads();

                slot = (slot + L) & 1023;
                outp += L;
            }
        }
    }
}

// ---------------- launcher ----------------
extern "C" void kernel_launch(void* const* d_in, const int* in_sizes, int n_in,
                              void* d_out, int out_size)
{
    const float* delay     = (const float*)d_in[0];  // [128]
    const float* raw_gain  = (const float*)d_in[1];  // [1]
    const float* raw_coeff = (const float*)d_in[2];  // [128,6]
    const float* exc       = (const float*)d_in[3];  // [1,65536,1]
    const float* burst     = (const float*)d_in[4];  // [65536]
    float* out = (float*)d_out;

    prep_kernel<<<1, 256>>>(delay, raw_gain, raw_coeff);
    sample_kernel<<<N_SAMPLES / 256, 256>>>(exc, burst);
    exc_scan_kernel<<<1, 1>>>(exc, burst);
    ks_kernel<<<1, 128>>>(out);
}

// round 8
// speedup vs baseline: 1.1112x; 1.1112x over previous
#include <cuda_runtime.h>
#include <math.h>

#define N_SAMPLES   65536
#define N_FRAMES    128
#define NUM_COEFF   6
#define NUM_ACTIVE  7
#define NSER        7
#define NSTAGE      5        // staging slots (4 cp.async groups in flight)

// ---------------- device scratch (no allocation allowed) ----------------
__device__ float  g_y[NSER][N_FRAMES];
__device__ float  g_M[NSER][N_FRAMES];
__device__ float4 g_A[N_SAMPLES];        // shifted weights w0..w3
__device__ float4 g_B[N_SAMPLES];        // shifted weights w4..w7
__device__ float2 g_C[N_SAMPLES];        // (x, bitcast ring window base w8)
__device__ int    g_minz;
__device__ int    g_maxz;
__device__ int    g_flag;

// ---------------- kernel A: coeff frames + spline tridiagonal solves ----------------
__global__ void prep_kernel(const float* __restrict__ delay,
                            const float* __restrict__ raw_gain,
                            const float* __restrict__ raw_coeff)
{
    __shared__ float s_y[NSER][N_FRAMES];
    __shared__ float s_cp[N_FRAMES];
    __shared__ float s_d[NSER][N_FRAMES];
    __shared__ float s_gain;

    const int tid = threadIdx.x;

    if (tid == 0) {
        s_gain = 1.0f / (1.0f + expf(-raw_gain[0]));
        g_minz = 0x7fffffff;
        g_maxz = 0;
        g_flag = 0;
        float c = 0.25f;
        s_cp[0] = c;
        for (int i = 1; i < N_FRAMES - 2; i++) {
            c = 1.0f / (4.0f - c);
            s_cp[i] = c;
        }
    }
    __syncthreads();

    for (int i = tid; i < N_FRAMES * NUM_COEFF; i += blockDim.x) {
        int r = i / NUM_COEFF, c = i % NUM_COEFF;
        s_y[1 + c][r] = 1.0f / (1.0f + expf(-raw_coeff[i]));
    }
    for (int r = tid; r < N_FRAMES; r += blockDim.x)
        s_y[0][r] = delay[r];
    __syncthreads();

    for (int r = tid; r < N_FRAMES; r += blockDim.x) {
        float sum = 0.0f;
        #pragma unroll
        for (int c = 0; c < NUM_COEFF; c++) sum += s_y[1 + c][r];
        float scale = s_gain / sum;
        #pragma unroll
        for (int c = 0; c < NUM_COEFF; c++) s_y[1 + c][r] *= scale;
    }
    __syncthreads();

    if (tid < NSER) {
        const int m = N_FRAMES - 2;
        const float K = 6.0f * 127.0f * 127.0f;
        float* y = s_y[tid];
        float* d = s_d[tid];

        float dp = K * (y[2] - 2.0f * y[1] + y[0]) * 0.25f;
        d[0] = dp;
        for (int i = 1; i < m; i++) {
            float rhs = K * (y[i + 2] - 2.0f * y[i + 1] + y[i]);
            dp = (rhs - dp) * s_cp[i];
            d[i] = dp;
        }
        g_M[tid][0] = 0.0f;
        g_M[tid][N_FRAMES - 1] = 0.0f;
        float Mn = 0.0f;
        for (int i = m - 1; i >= 0; i--) {
            Mn = d[i] - s_cp[i] * Mn;
            g_M[tid][i + 1] = Mn;
        }
    }
    __syncthreads();

    for (int i = tid; i < NSER * N_FRAMES; i += blockDim.x)
        (&g_y[0][0])[i] = (&s_y[0][0])[i];
}

// ---------------- kernel B: per-sample spline eval + SHIFTED tap weights ----
// Ring reads in ks_kernel are 4x LDS.64 over the aligned window
// f[i] = ring[w8 + i], i=0..7, where w8 = (pbH-6) & ~1 and
// pbH = ((t-1-z) & 1023) + 1024.  With d = (pbH-6) & 1, tap r_k = f[6+d-k],
// so storing w[6+d-k] = v[k] (zero padded) makes the scan a plain dot:
//   y = x - sum_i w[i] * f[i].
__global__ void sample_kernel(const float* __restrict__ exc,
                              const float* __restrict__ burst)
{
    const int t = blockIdx.x * blockDim.x + threadIdx.x;
    if (t >= N_SAMPLES) return;

    const float tt = (float)t * (1.0f / 65535.0f);
    int idx = (int)floorf(tt * 127.0f);
    idx = max(0, min(idx, 126));
    const float s  = tt - (float)idx * (1.0f / 127.0f);
    const float s2 = s * s;
    const float s3 = s2 * s;

    float vout[NSER];
    #pragma unroll
    for (int c = 0; c < NSER; c++) {
        float yi  = g_y[c][idx];
        float yi1 = g_y[c][idx + 1];
        float Mi  = g_M[c][idx];
        float Mi1 = g_M[c][idx + 1];
        float bsl = (yi1 - yi) * 127.0f - (2.0f * Mi + Mi1) * (1.0f / 762.0f);
        vout[c] = yi + bsl * s + 0.5f * Mi * s2 + (Mi1 - Mi) * s3 * (127.0f / 6.0f);
    }

    const float delay_i = vout[0];
    const int   z    = (int)floorf(delay_i);
    const float alfa = delay_i - (float)z;
    const float oma  = 1.0f - alfa;

    float v[7];
    v[0] = -oma * vout[1];
    #pragma unroll
    for (int k = 1; k < NUM_COEFF; k++)
        v[k] = -(alfa * vout[k] + oma * vout[k + 1]);
    v[6] = -alfa * vout[NUM_COEFF];

    const int pbH = ((t - 1 - z) & 1023) + 1024;
    const int d   = (pbH - 6) & 1;
    const int w8  = (pbH - 6) & ~1;

    float w[8];
    #pragma unroll
    for (int i = 0; i < 8; i++) w[i] = 0.0f;
    #pragma unroll
    for (int k = 0; k < 7; k++) w[6 + d - k] = v[k];

    g_A[t] = make_float4(w[0], w[1], w[2], w[3]);
    g_B[t] = make_float4(w[4], w[5], w[6], w[7]);
    g_C[t] = make_float2(burst[t], __int_as_float(w8));

    if (exc[t] != 0.0f) atomicExch(&g_flag, 1);

    int wmin = __reduce_min_sync(0xffffffffu, z);
    int wmax = __reduce_max_sync(0xffffffffu, z);
    if ((threadIdx.x & 31) == 0) {
        atomicMin(&g_minz, wmin);
        atomicMax(&g_maxz, wmax);
    }
}

// ---------------- kernel B2: general exc IIR fallback ----------------
__global__ void exc_scan_kernel(const float* __restrict__ exc,
                                const float* __restrict__ burst)
{
    if (g_flag) {
        float ym1 = 0.0f;
        for (int t = 0; t < N_SAMPLES; t++) {
            ym1 = burst[t] - exc[t] * ym1;
            g_C[t].x = ym1;
        }
    }
}

// ---------------- cp.async helpers ----------------
__device__ __forceinline__ void cpa16(void* dst_smem, const void* src) {
    unsigned d = (unsigned)__cvta_generic_to_shared(dst_smem);
    asm volatile("cp.async.ca.shared.global [%0], [%1], 16;"
                 :: "r"(d), "l"(src) : "memory");
}
__device__ __forceinline__ void cpa8(void* dst_smem, const void* src) {
    unsigned d = (unsigned)__cvta_generic_to_shared(dst_smem);
    asm volatile("cp.async.ca.shared.global [%0], [%1], 8;"
                 :: "r"(d), "l"(src) : "memory");
}

// ---------------- kernel C: chunk-parallel Karplus-Strong scan -------------
// R6 structure (best) with the ring reads cut from 7 scalar LDS to 4 LDS.64
// over an aligned window, and the alignment shift folded into precomputed
// weights (8-FMA unconditional dot).  Payload prefetched via cp.async
// (5 slots, 4 groups in flight) and read at use time (R7's register staging
// regressed).  Window bound: w8+7 <= 2047 always (w8 = (pbH-6)&~1,
// pbH <= 2047).  Duplicated-ring seam/zero arguments unchanged from R5.
__global__ void __launch_bounds__(128, 1) ks_kernel(float* __restrict__ out)
{
    __shared__ float  ring[2048];
    __shared__ float4 stA[NSTAGE][128];
    __shared__ float4 stB[NSTAGE][128];
    __shared__ float2 stC[NSTAGE][128];
    __shared__ int    sL;

    const int tid = threadIdx.x;
    #pragma unroll
    for (int i = tid; i < 2048; i += 128) ring[i] = 0.0f;

    if (tid == 0) {
        int L = g_minz + 1;
        if (L > 128) L = 128;
        int cap = 1024 - (g_maxz + NUM_ACTIVE) - 1;
        if (L > cap) L = cap;
        if (L < 1)  L = 1;
        sL = L;
    }
    __syncthreads();
    const int  L  = sL;
    const bool on = (tid < L);
    const int  nChunks = (N_SAMPLES + L - 1) / L;

    // prologue: chunks 0..3 -> slots 0..3 (4 groups in flight)
    #pragma unroll
    for (int s = 0; s < NSTAGE - 1; s++) {
        const int t = s * L + tid;
        if (on) {
            cpa16(&stA[s][tid], &g_A[t]);
            cpa16(&stB[s][tid], &g_B[t]);
            cpa8 (&stC[s][tid], &g_C[t]);
        }
        asm volatile("cp.async.commit_group;" ::: "memory");
    }

    int    slot = tid & 1023;                  // ring write slot (low copy)
    float* outp = out + tid;

    for (int c0 = 0; c0 < nChunks; c0 += NSTAGE) {
        #pragma unroll
        for (int s = 0; s < NSTAGE; s++) {
            const int c = c0 + s;
            if (c < nChunks) {
                // oldest outstanding group (chunk c, slot s) is done
                asm volatile("cp.async.wait_group 3;" ::: "memory");

                const float4 a  = stA[s][tid];
                const float4 b  = stB[s][tid];
                const float2 cc = stC[s][tid];

                // prefetch chunk c+4 into slot (s+4)%NSTAGE
                const int tp = (c + NSTAGE - 1) * L + tid;
                if (on && tp < N_SAMPLES) {
                    cpa16(&stA[(s + NSTAGE - 1) % NSTAGE][tid], &g_A[tp]);
                    cpa16(&stB[(s + NSTAGE - 1) % NSTAGE][tid], &g_B[tp]);
                    cpa8 (&stC[(s + NSTAGE - 1) % NSTAGE][tid], &g_C[tp]);
                }
                asm volatile("cp.async.commit_group;" ::: "memory");

                const int t = c * L + tid;
                if (on && t < N_SAMPLES) {
                    const int w8 = __float_as_int(cc.y);
                    float2 f0 = *reinterpret_cast<const float2*>(&ring[w8    ]);
                    float2 f1 = *reinterpret_cast<const float2*>(&ring[w8 + 2]);
                    float2 f2 = *reinterpret_cast<const float2*>(&ring[w8 + 4]);
                    float2 f3 = *reinterpret_cast<const float2*>(&ring[w8 + 6]);
                    float m0 = fmaf(a.x, f0.x, a.y * f0.y);
                    float m1 = fmaf(a.z, f1.x, a.w * f1.y);
                    float m2 = fmaf(b.x, f2.x, b.y * f2.y);
                    float m3 = fmaf(b.z, f3.x, b.w * f3.y);
                    float y  = cc.x - ((m0 + m1) + (m2 + m3));
                    ring[slot]        = y;
                    ring[slot + 1024] = y;
                    *outp = y;
                }
                __syncthreads();

                slot = (slot + L) & 1023;
                outp += L;
            }
        }
    }
}

// ---------------- launcher ----------------
extern "C" void kernel_launch(void* const* d_in, const int* in_sizes, int n_in,
                              void* d_out, int out_size)
{
    const float* delay     = (const float*)d_in[0];  // [128]
    const float* raw_gain  = (const float*)d_in[1];  // [1]
    const float* raw_coeff = (const float*)d_in[2];  // [128,6]
    const float* exc       = (const float*)d_in[3];  // [1,65536,1]
    const float* burst     = (const float*)d_in[4];  // [65536]
    float* out = (float*)d_out;

    prep_kernel<<<1, 256>>>(delay, raw_gain, raw_coeff);
    sample_kernel<<<N_SAMPLES / 256, 256>>>(exc, burst);
    exc_scan_kernel<<<1, 1>>>(exc, burst);
    ks_kernel<<<1, 128>>>(out);
}